// round 1
// baseline (speedup 1.0000x reference)
#include <cuda_runtime.h>
#include <cstdint>

// Problem constants (from reference)
#define B_  256
#define T_  256
#define AD_ 64
// floats per (b,t) row = 64 -> 16 float4
// total float4 = 256*256*16 = 1,048,576

__global__ __launch_bounds__(256)
void traj_kernel(const float* __restrict__ start_state,   // [B, 64]
                 const int*   __restrict__ instruction_id, // [B]
                 const float* __restrict__ patterns,       // [V, T, 64]
                 float*       __restrict__ out)            // [B, T, 64]
{
    // One float4 per thread.
    unsigned gid = blockIdx.x * blockDim.x + threadIdx.x;   // [0, B*T*16)
    // T*16 = 4096 float4 per batch row
    unsigned b   = gid >> 12;
    unsigned rem = gid & 4095u;
    unsigned t   = rem >> 4;
    unsigned a4  = rem & 15u;

    float prog = (float)t * (1.0f / (float)(T_ - 1));

    int iid = __ldg(&instruction_id[b]);

    const float4 s = __ldg((const float4*)(start_state + (size_t)b * AD_) + a4);
    const float4 p = __ldg((const float4*)(patterns + ((size_t)iid * T_ + t) * AD_) + a4);

    float4 r;
    r.x = fmaf(prog, p.x, s.x);
    r.y = fmaf(prog, p.y, s.y);
    r.z = fmaf(prog, p.z, s.z);
    r.w = fmaf(prog, p.w, s.w);

    ((float4*)out)[gid] = r;
}

extern "C" void kernel_launch(void* const* d_in, const int* in_sizes, int n_in,
                              void* d_out, int out_size)
{
    // Input order (metadata): 0 start_state, 1 instruction_id, 2 emb_W, 3 enc_W1,
    // 4 enc_b1, 5 enc_W2, 6 enc_b2, 7 s_W1, 8 s_b1, 9 s_W2, 10 s_b2, 11 p_W,
    // 12 p_b, 13 l0_Wih, 14 l0_Whh, 15 l0_bih, 16 l0_bhh, 17 l1_Wih, 18 l1_Whh,
    // 19 l1_bih, 20 l1_bhh, 21 e_W, 22 e_b, 23 a_W1, 24 a_b1, 25 a_W2, 26 a_b2,
    // 27 patterns
    const float* start_state    = (const float*)d_in[0];
    const int*   instruction_id = (const int*)  d_in[1];
    const float* patterns       = (const float*)d_in[27];
    float*       out            = (float*)d_out;

    const int total_f4 = B_ * T_ * (AD_ / 4);   // 1,048,576
    const int threads  = 256;
    const int blocks   = total_f4 / threads;    // 4096

    traj_kernel<<<blocks, threads>>>(start_state, instruction_id, patterns, out);
}

// round 2
// speedup vs baseline: 1.0036x; 1.0036x over previous
#include <cuda_runtime.h>
#include <cstdint>

// out[b,t,a] = start_state[b,a] + (t/(T-1)) * patterns[iid[b], t, a]
// B=256, T=256, AD=64 -> 16 float4 per (b,t) row.

#define B_   256
#define T_   256
#define AD_  64
#define F4_PER_ROW 16          // 64 floats / 4
#define TPB  256
#define T_PER_THREAD 4         // each thread: 4 t-values, same a4
// block covers one b and 64 consecutive t values:
//   256 threads = 16 t-rows x 16 a4-slots, x4 iterations over t (stride 16)
#define CHUNKS_PER_B 4         // 256 t / 64

__global__ __launch_bounds__(TPB)
void traj_kernel(const float* __restrict__ start_state,    // [B, 64]
                 const int*   __restrict__ instruction_id, // [B]
                 const float* __restrict__ patterns,       // [V, T, 64]
                 float*       __restrict__ out)            // [B, T, 64]
{
    const unsigned bid   = blockIdx.x;
    const unsigned b     = bid >> 2;          // 4 chunks per batch row
    const unsigned chunk = bid & 3u;
    const unsigned tid   = threadIdx.x;
    const unsigned a4    = tid & 15u;         // which float4 within the 64-float row
    const unsigned trow  = tid >> 4;          // 0..15
    const unsigned t0    = chunk * 64u + trow;

    const int iid = __ldg(&instruction_id[b]);

    const float4 s = __ldg((const float4*)(start_state + (size_t)b * AD_) + a4);

    const float4* __restrict__ pat =
        (const float4*)(patterns + (size_t)iid * T_ * AD_);
    float4* __restrict__ dst = (float4*)(out + (size_t)b * T_ * AD_);

    // 4 independent pattern loads issued back-to-back (MLP=4)
    float4 p[T_PER_THREAD];
    unsigned t[T_PER_THREAD];
#pragma unroll
    for (int i = 0; i < T_PER_THREAD; i++) {
        t[i] = t0 + (unsigned)i * 16u;
        p[i] = __ldg(pat + t[i] * F4_PER_ROW + a4);
    }

#pragma unroll
    for (int i = 0; i < T_PER_THREAD; i++) {
        const float prog = (float)t[i] * (1.0f / (float)(T_ - 1));
        float4 r;
        r.x = fmaf(prog, p[i].x, s.x);
        r.y = fmaf(prog, p[i].y, s.y);
        r.z = fmaf(prog, p[i].z, s.z);
        r.w = fmaf(prog, p[i].w, s.w);
        __stcs(dst + t[i] * F4_PER_ROW + a4, r);   // evict-first: output never reread
    }
}

extern "C" void kernel_launch(void* const* d_in, const int* in_sizes, int n_in,
                              void* d_out, int out_size)
{
    const float* start_state    = (const float*)d_in[0];
    const int*   instruction_id = (const int*)  d_in[1];
    const float* patterns       = (const float*)d_in[27];
    float*       out            = (float*)d_out;

    const int blocks = B_ * CHUNKS_PER_B;   // 1024
    traj_kernel<<<blocks, TPB>>>(start_state, instruction_id, patterns, out);
}

// round 3
// speedup vs baseline: 1.0257x; 1.0221x over previous
#include <cuda_runtime.h>
#include <cstdint>

// out[b,t,a] = start_state[b,a] + (t/(T-1)) * patterns[iid[b], t, a]
// B=256, T=256, AD=64 -> 16 float4 per (b,t) row.
//
// Key insight: patterns (65.5MB) + output (16.8MB) both fit in the 126MB L2.
// Under steady-state graph replay, pattern reads are L2 hits and the output
// lines stay dirty-resident in L2 (overwritten in place each replay) as long
// as we DON'T use evict-first stores. So: default write-back stores.

#define B_   256
#define T_   256
#define AD_  64
#define F4_PER_ROW 16          // 64 floats / 4
#define TPB  256
#define T_PER_THREAD 4
#define CHUNKS_PER_B 4         // 256 t / (16 trows * 4 iters)

__global__ __launch_bounds__(TPB)
void traj_kernel(const float* __restrict__ start_state,    // [B, 64]
                 const int*   __restrict__ instruction_id, // [B]
                 const float* __restrict__ patterns,       // [V, T, 64]
                 float*       __restrict__ out)            // [B, T, 64]
{
    const unsigned bid   = blockIdx.x;
    const unsigned b     = bid >> 2;
    const unsigned chunk = bid & 3u;
    const unsigned tid   = threadIdx.x;
    const unsigned a4    = tid & 15u;          // float4 slot within 64-float row
    const unsigned trow  = tid >> 4;           // 0..15
    const unsigned t0    = chunk * 64u + trow;

    const int iid = __ldg(&instruction_id[b]);

    const float4 s = __ldg((const float4*)(start_state + (size_t)b * AD_) + a4);

    const float4* __restrict__ pat =
        (const float4*)(patterns + (size_t)iid * T_ * AD_);
    float4* __restrict__ dst = (float4*)(out + (size_t)b * T_ * AD_);

    // 4 independent pattern loads issued back-to-back (MLP=4)
    float4 p[T_PER_THREAD];
    unsigned t[T_PER_THREAD];
#pragma unroll
    for (int i = 0; i < T_PER_THREAD; i++) {
        t[i] = t0 + (unsigned)i * 16u;
        p[i] = __ldg(pat + t[i] * F4_PER_ROW + a4);
    }

#pragma unroll
    for (int i = 0; i < T_PER_THREAD; i++) {
        const float prog = (float)t[i] * (1.0f / (float)(T_ - 1));
        float4 r;
        r.x = fmaf(prog, p[i].x, s.x);
        r.y = fmaf(prog, p[i].y, s.y);
        r.z = fmaf(prog, p[i].z, s.z);
        r.w = fmaf(prog, p[i].w, s.w);
        dst[t[i] * F4_PER_ROW + a4] = r;       // default write-back: stay L2-resident
    }
}

extern "C" void kernel_launch(void* const* d_in, const int* in_sizes, int n_in,
                              void* d_out, int out_size)
{
    const float* start_state    = (const float*)d_in[0];
    const int*   instruction_id = (const int*)  d_in[1];
    const float* patterns       = (const float*)d_in[27];
    float*       out            = (float*)d_out;

    const int blocks = B_ * CHUNKS_PER_B;   // 1024
    traj_kernel<<<blocks, TPB>>>(start_state, instruction_id, patterns, out);
}